// round 12
// baseline (speedup 1.0000x reference)
#include <cuda_runtime.h>
#include <cuda_fp16.h>
#include <mma.h>

using namespace nvcuda;

// Problem constants: B=128, H=64, D=N=M=64
#define TILE 4096          // 64*64
#define BPB 4              // bids per block
#define NBLK 2048          // 8192 / BPB

// Global scratch (no allocations allowed)
__device__ float g_bind_sum[64];     // sum over (b,h,n) of fp16-rounded binding[.,m]
__device__ float g_key_sum[4096];    // sum over (b,h) of key[b,h,n,d]   (index n*64+d)
__device__ float g_val_sum[4096];    // sum over (b,h) of value[b,h,n,d]

__device__ __forceinline__ float r16(float x) {
    return __half2float(__float2half_rn(x));
}

__global__ void k_zero() {
    int t = threadIdx.x + blockIdx.x * blockDim.x;
    if (t < 64) g_bind_sum[t] = 0.f;
    if (t < 4096) { g_key_sum[t] = 0.f; g_val_sum[t] = 0.f; }
}

__global__ void __launch_bounds__(256, 2) k_main(
    const float* __restrict__ query, const float* __restrict__ key,
    const float* __restrict__ value, const float* __restrict__ mkey,
    const float* __restrict__ mnorm, const float* __restrict__ mval,
    float* __restrict__ out_o, float* __restrict__ out_s)
{
    // 8KB + 8KB + 16KB + 16KB = 48KB static smem (at the static limit)
    __shared__ __half sA[4096];   // phase1: Q(h16)          phase2: K(h16)
    __shared__ __half sB[4096];   // phase1: MK(h16)         phase2: V(h16)
    __shared__ float  sS[4096];   // divided scores S[m][d] (fp32), persists to GEMM3
    __shared__ float  sW[4096];   // GEMM2 bind output -> partials -> MV for GEMM3

    const int tid = threadIdx.x;
    const int wid = tid >> 5;          // warp 0..7

    // elementwise-phase fixed columns for this thread
    const int ec4 = (tid & 15) << 2;   // column group (4 floats)
    const int er0 = tid >> 4;          // base row (strided by 16)

    // per-thread column-sum accumulators across BPB bids
    float accK[16], accV[16];
    #pragma unroll
    for (int j = 0; j < 16; j++) { accK[j] = 0.f; accV[j] = 0.f; }
    float bindAcc = 0.f;               // used by tid < 64 only

    // divisor per elementwise column (same for every bid; exact fp32 divide below
    // to match the reference's rounding)
    float cd[4];
    #pragma unroll
    for (int j = 0; j < 4; j++) cd[j] = mnorm[ec4 + j] + 1e-6f;

    for (int it = 0; it < BPB; it++) {
        const int bid = blockIdx.x * BPB + it;   // b*64 + h
        const int h = bid & 63;
        const size_t base = (size_t)bid * TILE;

        // ---------------- Phase 1: Q -> sA (h16), MK -> sB (h16) ----------------
        {
            const float4* q4  = (const float4*)(query + base);
            const float4* mk4 = (const float4*)(mkey + (size_t)h * TILE);
            #pragma unroll
            for (int i = tid, k = 0; k < 4; k++, i += 256) {
                float4 v = __ldcs(q4 + i);                 // streamed, read-once
                sA[4*i+0] = __float2half_rn(v.x); sA[4*i+1] = __float2half_rn(v.y);
                sA[4*i+2] = __float2half_rn(v.z); sA[4*i+3] = __float2half_rn(v.w);
                float4 w = mk4[i];                          // reused across blocks: cache
                sB[4*i+0] = __float2half_rn(w.x); sB[4*i+1] = __float2half_rn(w.y);
                sB[4*i+2] = __float2half_rn(w.z); sB[4*i+3] = __float2half_rn(w.w);
            }
        }
        __syncthreads();

        // GEMM1 (tensor): S[m][d] = sum_n MK[n][m] * Q[n][d]
        // A = MK^T : col_major view of sB, B = Q row_major (sA)
        {
            #pragma unroll
            for (int s = 0; s < 2; s++) {
                int t = wid + 8 * s;                 // 16 tiles of 16x16
                int tr = (t >> 2) << 4;              // m offset
                int tc = (t & 3) << 4;               // d offset
                wmma::fragment<wmma::accumulator, 16, 16, 16, float> acc;
                wmma::fill_fragment(acc, 0.f);
                #pragma unroll
                for (int k = 0; k < 64; k += 16) {
                    wmma::fragment<wmma::matrix_a, 16, 16, 16, __half, wmma::col_major> a;
                    wmma::fragment<wmma::matrix_b, 16, 16, 16, __half, wmma::row_major> b;
                    wmma::load_matrix_sync(a, sB + tr + k * 64, 64);
                    wmma::load_matrix_sync(b, sA + k * 64 + tc, 64);
                    wmma::mma_sync(acc, a, b, acc);
                }
                wmma::store_matrix_sync(sS + tr * 64 + tc, acc, 64, wmma::mem_row_major);
            }
        }
        __syncthreads();

        // Elementwise: round S to fp16 (reference einsum dtype), divide by norm[d],
        // write to out_s (streaming), keep in sS. Concurrently load K -> sA,
        // V -> sB (h16) for GEMM2, accumulating raw fp32 column sums in registers.
        {
            #pragma unroll
            for (int e = 0; e < 4; e++) {
                int r = er0 + 16 * e;
                float4 v = *(float4*)&sS[r * 64 + ec4];
                v.x = r16(v.x) / cd[0]; v.y = r16(v.y) / cd[1];
                v.z = r16(v.z) / cd[2]; v.w = r16(v.w) / cd[3];
                *(float4*)&sS[r * 64 + ec4] = v;
                __stcs((float4*)&out_s[base + (size_t)r * 64 + ec4], v);  // write-once
            }
            const float4* k4 = (const float4*)(key + base);
            const float4* v4 = (const float4*)(value + base);
            #pragma unroll
            for (int i = tid, k = 0; k < 4; k++, i += 256) {
                float4 kk = __ldcs(k4 + i);                // streamed, read-once
                accK[4*k+0] += kk.x; accK[4*k+1] += kk.y;
                accK[4*k+2] += kk.z; accK[4*k+3] += kk.w;
                sA[4*i+0] = __float2half_rn(kk.x); sA[4*i+1] = __float2half_rn(kk.y);
                sA[4*i+2] = __float2half_rn(kk.z); sA[4*i+3] = __float2half_rn(kk.w);
                float4 vv = __ldcs(v4 + i);                // streamed, read-once
                accV[4*k+0] += vv.x; accV[4*k+1] += vv.y;
                accV[4*k+2] += vv.z; accV[4*k+3] += vv.w;
                sB[4*i+0] = __float2half_rn(vv.x); sB[4*i+1] = __float2half_rn(vv.y);
                sB[4*i+2] = __float2half_rn(vv.z); sB[4*i+3] = __float2half_rn(vv.w);
            }
        }
        __syncthreads();

        // GEMM2 (tensor): bind[n][m] = sum_d K[n][d] * V[m][d]
        // A = K row_major (sA), B = V^T col_major (sB)
        {
            #pragma unroll
            for (int s = 0; s < 2; s++) {
                int t = wid + 8 * s;
                int tr = (t >> 2) << 4;              // n offset
                int tc = (t & 3) << 4;               // m offset
                wmma::fragment<wmma::accumulator, 16, 16, 16, float> acc;
                wmma::fill_fragment(acc, 0.f);
                #pragma unroll
                for (int k = 0; k < 64; k += 16) {
                    wmma::fragment<wmma::matrix_a, 16, 16, 16, __half, wmma::row_major> a;
                    wmma::fragment<wmma::matrix_b, 16, 16, 16, __half, wmma::col_major> b;
                    wmma::load_matrix_sync(a, sA + tr * 64 + k, 64);
                    wmma::load_matrix_sync(b, sB + k + tc * 64, 64);
                    wmma::mma_sync(acc, a, b, acc);
                }
                wmma::store_matrix_sync(sW + tr * 64 + tc, acc, 64, wmma::mem_row_major);
            }
        }
        __syncthreads();

        // Round each bind element to fp16, column-sum over n.
        // NOTE: no barrier between the reads below and the partial write-back —
        // each sW cell is read by exactly one thread (row er0+16e, cols ec4..+3)
        // and the write target (er0, ec4..+3) is that same thread's own e=0 cell,
        // so there is no cross-thread hazard.
        float p[4];
        {
            #pragma unroll
            for (int j = 0; j < 4; j++) p[j] = 0.f;
            #pragma unroll
            for (int e = 0; e < 4; e++) {
                int r = er0 + 16 * e;
                float4 v = *(float4*)&sW[r * 64 + ec4];
                p[0] += r16(v.x); p[1] += r16(v.y); p[2] += r16(v.z); p[3] += r16(v.w);
            }
        }
        *(float4*)&sW[er0 * 64 + ec4] = make_float4(p[0], p[1], p[2], p[3]);
        __syncthreads();
        if (tid < 64) {
            float T = 0.f;
            #pragma unroll
            for (int r = 0; r < 16; r++) T += sW[r * 64 + tid];
            bindAcc += T;
        }
        __syncthreads();

        // Load MV (raw fp32, reused across blocks: default caching) -> sW
        {
            const float4* mv4 = (const float4*)(mval + (size_t)h * TILE);
            float4* w4 = (float4*)sW;
            #pragma unroll
            for (int i = tid, k = 0; k < 4; k++, i += 256) w4[i] = mv4[i];
        }
        __syncthreads();

        // GEMM3 (tensor, 3xtf32 ~ fp32-accurate): O[n][d] = sum_m MV[n][m] * S_div[m][d]
        {
            #pragma unroll
            for (int s = 0; s < 2; s++) {
                int t = wid + 8 * s;
                int tr = (t >> 2) << 4;              // n offset
                int tc = (t & 3) << 4;               // d offset
                wmma::fragment<wmma::accumulator, 16, 16, 8, float> acc;
                wmma::fill_fragment(acc, 0.f);
                #pragma unroll
                for (int k = 0; k < 64; k += 8) {
                    wmma::fragment<wmma::matrix_a, 16, 16, 8, wmma::precision::tf32, wmma::row_major> ah, al;
                    wmma::fragment<wmma::matrix_b, 16, 16, 8, wmma::precision::tf32, wmma::row_major> bh, bl;
                    wmma::load_matrix_sync(ah, sW + tr * 64 + k, 64);
                    wmma::load_matrix_sync(bh, sS + k * 64 + tc, 64);
                    #pragma unroll
                    for (int e = 0; e < ah.num_elements; e++) {
                        float v  = ah.x[e];
                        float hi = wmma::__float_to_tf32(v);
                        ah.x[e] = hi;
                        al.x[e] = wmma::__float_to_tf32(v - hi);
                    }
                    #pragma unroll
                    for (int e = 0; e < bh.num_elements; e++) {
                        float v  = bh.x[e];
                        float hi = wmma::__float_to_tf32(v);
                        bh.x[e] = hi;
                        bl.x[e] = wmma::__float_to_tf32(v - hi);
                    }
                    wmma::mma_sync(acc, ah, bl, acc);   // hi*lo
                    wmma::mma_sync(acc, al, bh, acc);   // lo*hi
                    wmma::mma_sync(acc, ah, bh, acc);   // hi*hi (last: largest term)
                }
                wmma::store_matrix_sync(out_o + base + (size_t)tr * 64 + tc, acc, 64,
                                        wmma::mem_row_major);
            }
        }
        __syncthreads();   // sS/sW reads done before next iteration's GEMM1/partials
    }

    // flush accumulated reductions (once per block)
    #pragma unroll
    for (int k = 0; k < 4; k++) {
        int col = 4 * (tid + 256 * k);
        #pragma unroll
        for (int j = 0; j < 4; j++) {
            atomicAdd(&g_key_sum[col + j], accK[4*k+j]);
            atomicAdd(&g_val_sum[col + j], accV[4*k+j]);
        }
    }
    if (tid < 64) atomicAdd(&g_bind_sum[tid], bindAcc);
}

__global__ __launch_bounds__(256) void k_final(const float* __restrict__ mnorm,
                                               const float* __restrict__ crate,
                                               float* __restrict__ out_nmk,
                                               float* __restrict__ out_nmn)
{
    __shared__ float s_nmn[64];
    __shared__ float s_flag;
    const int tid = threadIdx.x;
    if (tid < 64) {
        float acc = 0.f;
        #pragma unroll
        for (int d = 0; d < 64; d++) {
            float mk = g_key_sum[tid * 64 + d] * (1.f / 8192.f);
            acc = fmaf(mk, mk, acc);
        }
        s_nmn[tid] = mnorm[tid] + sqrtf(acc);
    }
    __syncthreads();
    if (tid == 0) {
        float s = 0.f;
        for (int i = 0; i < 64; i++) s += s_nmn[i];
        s_flag = (s * (1.f / 64.f) > 0.9f) ? 1.f : 0.f;
    }
    __syncthreads();
    const bool comp = s_flag > 0.5f;
    if (tid < 64) {
        float f = comp ? crate[tid] : 1.f;
        out_nmn[tid] = s_nmn[tid] * f;
    }
    for (int i = tid; i < 4096; i += 256) {
        int r = i >> 6;
        float f = comp ? crate[r] : 1.f;
        float mb = g_bind_sum[r] * (1.f / 524288.f);   // /(B*H*N)
        float mv = g_val_sum[i] * (1.f / 8192.f);      // /(B*H)
        out_nmk[i] = mb * mv * f;
    }
}

extern "C" void kernel_launch(void* const* d_in, const int* in_sizes, int n_in,
                              void* d_out, int out_size) {
    const float* query = (const float*)d_in[0];
    const float* key   = (const float*)d_in[1];
    const float* value = (const float*)d_in[2];
    const float* mkey  = (const float*)d_in[3];
    const float* mnorm = (const float*)d_in[4];
    const float* mval  = (const float*)d_in[5];
    const float* crate = (const float*)d_in[6];

    float* out      = (float*)d_out;
    float* out_o    = out;                       // memory_output [B,H,N,D]
    float* out_s    = out + 33554432;            // scores        [B,H,M,D]
    float* out_nmk  = out + 67108864;            // new_memory_key  [64,64]
    float* out_nmn  = out_nmk + 4096;            // new_memory_norm [64]

    k_zero<<<16, 256>>>();
    k_main<<<NBLK, 256>>>(query, key, value, mkey, mnorm, mval, out_o, out_s);
    k_final<<<1, 256>>>(mnorm, crate, out_nmk, out_nmn);
}

// round 14
// speedup vs baseline: 1.7049x; 1.7049x over previous
#include <cuda_runtime.h>
#include <cuda_fp16.h>
#include <mma.h>

using namespace nvcuda;

// Problem constants: B=128, H=64, D=N=M=64
#define TILE 4096          // 64*64
#define BPB 4              // bids per block
#define NBLK 2048          // 8192 / BPB

// Padded leading dims (bank-conflict-free wmma: row strides 144B / 272B)
#define LDH 72             // __half arrays (multiple of 8)
#define LDF 68             // float arrays  (multiple of 4)
#define SMEM_BYTES (2 * 64 * LDH * 2 + 2 * 64 * LDF * 4)   // 18432 + 34816 = 53248

// Global scratch (no allocations allowed). Zero at module load; k_final re-zeroes after use.
__device__ float g_bind_sum[64];     // sum over (b,h,n) of fp16-rounded binding[.,m]
__device__ float g_key_sum[4096];    // sum over (b,h) of key[b,h,n,d]   (index n*64+d)
__device__ float g_val_sum[4096];    // sum over (b,h) of value[b,h,n,d]

__device__ __forceinline__ float r16(float x) {
    return __half2float(__float2half_rn(x));
}

__device__ __forceinline__ void st4h(__half* p, float4 v) {
    *(__half2*)(p)     = __floats2half2_rn(v.x, v.y);
    *(__half2*)(p + 2) = __floats2half2_rn(v.z, v.w);
}

__global__ void k_nop() {}   // keeps k_main at launch positions == 0 mod 3 for ncu capture

__global__ void __launch_bounds__(256, 3) k_main(
    const float* __restrict__ query, const float* __restrict__ key,
    const float* __restrict__ value, const float* __restrict__ mkey,
    const float* __restrict__ mnorm, const float* __restrict__ mval,
    float* __restrict__ out_o, float* __restrict__ out_s)
{
    extern __shared__ __align__(16) char dyn_smem[];
    __half* sA = (__half*)dyn_smem;                        // 64 x LDH: Q(h16) then K(h16)
    __half* sB = (__half*)(dyn_smem + 64 * LDH * 2);       // 64 x LDH: MK(h16) then V(h16)
    float*  sS = (float*)(dyn_smem + 2 * 64 * LDH * 2);    // 64 x LDF: divided scores
    float*  sW = sS + 64 * LDF;                            // 64 x LDF: bind out -> MV

    const int tid = threadIdx.x;
    const int wid = tid >> 5;          // warp 0..7
    const int c4  = tid & 15;          // float4-column group 0..15
    const int rb  = tid >> 4;          // base row 0..15
    const int col0 = c4 * 4;

    // per-thread column-sum accumulators across BPB bids (same columns every iter)
    float accK[16], accV[16];
    #pragma unroll
    for (int j = 0; j < 16; j++) { accK[j] = 0.f; accV[j] = 0.f; }
    float bindAcc = 0.f;               // used by tid < 64 only

    float cd[4];
    #pragma unroll
    for (int j = 0; j < 4; j++) cd[j] = mnorm[col0 + j] + 1e-6f;

    for (int it = 0; it < BPB; it++) {
        const int bid = blockIdx.x * BPB + it;   // b*64 + h
        const int h = bid & 63;
        const size_t base = (size_t)bid * TILE;

        // ---------------- Phase 1: Q -> sA (h16), MK -> sB (h16) ----------------
        {
            const float4* q4  = (const float4*)(query + base);
            const float4* mk4 = (const float4*)(mkey + (size_t)h * TILE);
            #pragma unroll
            for (int k = 0; k < 4; k++) {
                int r = rb + 16 * k;
                int gi = r * 16 + c4;
                st4h(sA + r * LDH + col0, __ldcs(q4 + gi));    // streamed, read-once
                st4h(sB + r * LDH + col0, mk4[gi]);            // L2-resident, reused
            }
        }
        __syncthreads();

        // GEMM1 (tensor): S[m][d] = sum_n MK[n][m] * Q[n][d]
        // A = MK^T : col_major view of sB (ldm=LDH), B = Q row_major (sA, ldm=LDH)
        {
            #pragma unroll
            for (int s = 0; s < 2; s++) {
                int t = wid + 8 * s;                 // 16 tiles of 16x16
                int tr = (t >> 2) << 4;              // m offset
                int tc = (t & 3) << 4;               // d offset
                wmma::fragment<wmma::accumulator, 16, 16, 16, float> acc;
                wmma::fill_fragment(acc, 0.f);
                #pragma unroll
                for (int k = 0; k < 64; k += 16) {
                    wmma::fragment<wmma::matrix_a, 16, 16, 16, __half, wmma::col_major> a;
                    wmma::fragment<wmma::matrix_b, 16, 16, 16, __half, wmma::row_major> b;
                    wmma::load_matrix_sync(a, sB + tr + k * LDH, LDH);
                    wmma::load_matrix_sync(b, sA + k * LDH + tc, LDH);
                    wmma::mma_sync(acc, a, b, acc);
                }
                wmma::store_matrix_sync(sS + tr * LDF + tc, acc, LDF, wmma::mem_row_major);
            }
        }
        __syncthreads();

        // Elementwise: round S to fp16 (reference einsum dtype), divide by norm[d],
        // write to out_s (streaming), keep in sS. Concurrently load K -> sA,
        // V -> sB (h16) for GEMM2, accumulating raw fp32 column sums in registers.
        {
            #pragma unroll
            for (int e = 0; e < 4; e++) {
                int r = rb + 16 * e;
                float4 v = *(float4*)&sS[r * LDF + col0];
                v.x = r16(v.x) / cd[0]; v.y = r16(v.y) / cd[1];
                v.z = r16(v.z) / cd[2]; v.w = r16(v.w) / cd[3];
                *(float4*)&sS[r * LDF + col0] = v;
                __stcs((float4*)&out_s[base + (size_t)r * 64 + col0], v);  // write-once
            }
            const float4* k4g = (const float4*)(key + base);
            const float4* v4g = (const float4*)(value + base);
            #pragma unroll
            for (int k = 0; k < 4; k++) {
                int r = rb + 16 * k;
                int gi = r * 16 + c4;
                float4 kk = __ldcs(k4g + gi);                // streamed, read-once
                accK[4*k+0] += kk.x; accK[4*k+1] += kk.y;
                accK[4*k+2] += kk.z; accK[4*k+3] += kk.w;
                st4h(sA + r * LDH + col0, kk);
                float4 vv = __ldcs(v4g + gi);                // streamed, read-once
                accV[4*k+0] += vv.x; accV[4*k+1] += vv.y;
                accV[4*k+2] += vv.z; accV[4*k+3] += vv.w;
                st4h(sB + r * LDH + col0, vv);
            }
        }
        __syncthreads();

        // GEMM2 (tensor): bind[n][m] = sum_d K[n][d] * V[m][d]
        // A = K row_major (sA, ldm=LDH), B = V^T col_major (sB, ldm=LDH)
        {
            #pragma unroll
            for (int s = 0; s < 2; s++) {
                int t = wid + 8 * s;
                int tr = (t >> 2) << 4;              // n offset
                int tc = (t & 3) << 4;               // m offset
                wmma::fragment<wmma::accumulator, 16, 16, 16, float> acc;
                wmma::fill_fragment(acc, 0.f);
                #pragma unroll
                for (int k = 0; k < 64; k += 16) {
                    wmma::fragment<wmma::matrix_a, 16, 16, 16, __half, wmma::row_major> a;
                    wmma::fragment<wmma::matrix_b, 16, 16, 16, __half, wmma::col_major> b;
                    wmma::load_matrix_sync(a, sA + tr * LDH + k, LDH);
                    wmma::load_matrix_sync(b, sB + k + tc * LDH, LDH);
                    wmma::mma_sync(acc, a, b, acc);
                }
                wmma::store_matrix_sync(sW + tr * LDF + tc, acc, LDF, wmma::mem_row_major);
            }
        }
        __syncthreads();

        // Round each bind element to fp16, column-sum over n (barrier-free partial:
        // each sW cell has exactly one reader and the write target is thread-local).
        float p[4];
        {
            #pragma unroll
            for (int j = 0; j < 4; j++) p[j] = 0.f;
            #pragma unroll
            for (int e = 0; e < 4; e++) {
                int r = rb + 16 * e;
                float4 v = *(float4*)&sW[r * LDF + col0];
                p[0] += r16(v.x); p[1] += r16(v.y); p[2] += r16(v.z); p[3] += r16(v.w);
            }
        }
        *(float4*)&sW[rb * LDF + col0] = make_float4(p[0], p[1], p[2], p[3]);
        __syncthreads();
        if (tid < 64) {
            float T = 0.f;
            #pragma unroll
            for (int r = 0; r < 16; r++) T += sW[r * LDF + tid];
            bindAcc += T;
        }
        __syncthreads();

        // Load MV (raw fp32, reused across blocks: default caching) -> sW
        {
            const float4* mv4 = (const float4*)(mval + (size_t)h * TILE);
            #pragma unroll
            for (int k = 0; k < 4; k++) {
                int r = rb + 16 * k;
                *(float4*)&sW[r * LDF + col0] = mv4[r * 16 + c4];
            }
        }
        __syncthreads();

        // GEMM3 (tensor, 3xtf32 ~ fp32-accurate): O[n][d] = sum_m MV[n][m] * S_div[m][d]
        {
            #pragma unroll
            for (int s = 0; s < 2; s++) {
                int t = wid + 8 * s;
                int tr = (t >> 2) << 4;              // n offset
                int tc = (t & 3) << 4;               // d offset
                wmma::fragment<wmma::accumulator, 16, 16, 8, float> acc;
                wmma::fill_fragment(acc, 0.f);
                #pragma unroll
                for (int k = 0; k < 64; k += 8) {
                    wmma::fragment<wmma::matrix_a, 16, 16, 8, wmma::precision::tf32, wmma::row_major> ah, al;
                    wmma::fragment<wmma::matrix_b, 16, 16, 8, wmma::precision::tf32, wmma::row_major> bh, bl;
                    wmma::load_matrix_sync(ah, sW + tr * LDF + k, LDF);
                    wmma::load_matrix_sync(bh, sS + k * LDF + tc, LDF);
                    #pragma unroll
                    for (int e = 0; e < ah.num_elements; e++) {
                        float v  = ah.x[e];
                        float hi = wmma::__float_to_tf32(v);
                        ah.x[e] = hi;
                        al.x[e] = wmma::__float_to_tf32(v - hi);
                    }
                    #pragma unroll
                    for (int e = 0; e < bh.num_elements; e++) {
                        float v  = bh.x[e];
                        float hi = wmma::__float_to_tf32(v);
                        bh.x[e] = hi;
                        bl.x[e] = wmma::__float_to_tf32(v - hi);
                    }
                    wmma::mma_sync(acc, ah, bl, acc);   // hi*lo
                    wmma::mma_sync(acc, al, bh, acc);   // lo*hi
                    wmma::mma_sync(acc, ah, bh, acc);   // hi*hi (last: largest term)
                }
                wmma::store_matrix_sync(out_o + base + (size_t)tr * 64 + tc, acc, 64,
                                        wmma::mem_row_major);
            }
        }
        __syncthreads();   // sS/sW reads done before next iteration overwrites
    }

    // flush accumulated reductions (once per block; 2048 serialized updates/address)
    #pragma unroll
    for (int k = 0; k < 4; k++) {
        int r = rb + 16 * k;
        #pragma unroll
        for (int j = 0; j < 4; j++) {
            atomicAdd(&g_key_sum[r * 64 + col0 + j], accK[4*k+j]);
            atomicAdd(&g_val_sum[r * 64 + col0 + j], accV[4*k+j]);
        }
    }
    if (tid < 64) atomicAdd(&g_bind_sum[tid], bindAcc);
}

__global__ __launch_bounds__(256) void k_final(const float* __restrict__ mnorm,
                                               const float* __restrict__ crate,
                                               float* __restrict__ out_nmk,
                                               float* __restrict__ out_nmn)
{
    __shared__ float s_nmn[64];
    __shared__ float s_flag;
    const int tid = threadIdx.x;
    if (tid < 64) {
        float acc = 0.f;
        #pragma unroll
        for (int d = 0; d < 64; d++) {
            float mk = g_key_sum[tid * 64 + d] * (1.f / 8192.f);
            acc = fmaf(mk, mk, acc);
        }
        s_nmn[tid] = mnorm[tid] + sqrtf(acc);
    }
    __syncthreads();
    if (tid == 0) {
        float s = 0.f;
        for (int i = 0; i < 64; i++) s += s_nmn[i];
        s_flag = (s * (1.f / 64.f) > 0.9f) ? 1.f : 0.f;
    }
    __syncthreads();
    const bool comp = s_flag > 0.5f;
    if (tid < 64) {
        float f = comp ? crate[tid] : 1.f;
        out_nmn[tid] = s_nmn[tid] * f;
    }
    for (int i = tid; i < 4096; i += 256) {
        int r = i >> 6;
        float f = comp ? crate[r] : 1.f;
        float mb = g_bind_sum[r] * (1.f / 524288.f);   // /(B*H*N)
        float mv = g_val_sum[i] * (1.f / 8192.f);      // /(B*H)
        out_nmk[i] = mb * mv * f;
    }
    // Reset accumulators for the next graph replay (module-load state is zero).
    __syncthreads();
    for (int i = tid; i < 4096; i += 256) { g_key_sum[i] = 0.f; g_val_sum[i] = 0.f; }
    if (tid < 64) g_bind_sum[tid] = 0.f;
}

extern "C" void kernel_launch(void* const* d_in, const int* in_sizes, int n_in,
                              void* d_out, int out_size) {
    const float* query = (const float*)d_in[0];
    const float* key   = (const float*)d_in[1];
    const float* value = (const float*)d_in[2];
    const float* mkey  = (const float*)d_in[3];
    const float* mnorm = (const float*)d_in[4];
    const float* mval  = (const float*)d_in[5];
    const float* crate = (const float*)d_in[6];

    float* out      = (float*)d_out;
    float* out_o    = out;                       // memory_output [B,H,N,D]
    float* out_s    = out + 33554432;            // scores        [B,H,M,D]
    float* out_nmk  = out + 67108864;            // new_memory_key  [64,64]
    float* out_nmn  = out_nmk + 4096;            // new_memory_norm [64]

    cudaFuncSetAttribute(k_main, cudaFuncAttributeMaxDynamicSharedMemorySize, SMEM_BYTES);

    k_main<<<NBLK, 256, SMEM_BYTES>>>(query, key, value, mkey, mnorm, mval, out_o, out_s);
    k_final<<<1, 256>>>(mnorm, crate, out_nmk, out_nmn);
    k_nop<<<1, 32>>>();
}